// round 9
// baseline (speedup 1.0000x reference)
#include <cuda_runtime.h>
#include <cuda_fp16.h>
#include <cstdint>
#include <cstddef>

// out[4096,4096] = half(x)[4096,4096] @ half(W)^T + half(bias)
// E5M10 RNE quantize == __float2half_rn exactly for these inputs.
// Base sm_103 ISA (no tcgen05): cp.async + ldmatrix + mma.sync HMMA.
// R9: keep R7 (3-stage ring, 2 CTA/SM). Pipeline fragments inside the stage:
//     B-frags double-buffered, A-frags rotated f-major after last use,
//     cp.async issue moved after the ks0 fragment loads.

#define ND 4096

static constexpr int BM = 128;
static constexpr int BN = 128;
static constexpr int BK = 64;            // 64 halves = 128 B rows
static constexpr int STAGES = 3;
static constexpr int NTHREADS = 256;

static constexpr int A_BYTES = BM * 128;              // 16 KB
static constexpr int B_BYTES = BN * 128;              // 16 KB
static constexpr int STAGE_BYTES = A_BYTES + B_BYTES; // 32 KB
static constexpr int SMEM_BYTES = STAGES * STAGE_BYTES; // 96 KB -> 2 CTAs/SM

// __device__ scratch (no runtime allocation allowed)
__device__ __half g_qA[(size_t)ND * ND];
__device__ __half g_qB[(size_t)ND * ND];
__device__ float  g_qbias[ND];

// ---------------- helpers ----------------
__device__ __forceinline__ uint32_t smem_u32(const void* p) {
    uint32_t a;
    asm("{ .reg .u64 t; cvta.to.shared.u64 t, %1; cvt.u32.u64 %0, t; }" : "=r"(a) : "l"(p));
    return a;
}

__device__ __forceinline__ void ldmatrix_x4(uint32_t& r0, uint32_t& r1, uint32_t& r2,
                                            uint32_t& r3, uint32_t addr) {
    asm volatile("ldmatrix.sync.aligned.m8n8.x4.shared.b16 {%0,%1,%2,%3}, [%4];"
                 : "=r"(r0), "=r"(r1), "=r"(r2), "=r"(r3) : "r"(addr));
}

__device__ __forceinline__ void mma_16816(float* c, const uint32_t* a,
                                          uint32_t b0, uint32_t b1) {
    asm volatile(
        "mma.sync.aligned.m16n8k16.row.col.f32.f16.f16.f32 "
        "{%0,%1,%2,%3}, {%4,%5,%6,%7}, {%8,%9}, {%0,%1,%2,%3};"
        : "+f"(c[0]), "+f"(c[1]), "+f"(c[2]), "+f"(c[3])
        : "r"(a[0]), "r"(a[1]), "r"(a[2]), "r"(a[3]), "r"(b0), "r"(b1));
}

// ---------------- quantize pass ----------------
__global__ void __launch_bounds__(256) quantize_kernel(
    const float* __restrict__ x, const float* __restrict__ w, const float* __restrict__ b) {
    size_t i = (size_t)blockIdx.x * blockDim.x + threadIdx.x;
    const size_t n4 = (size_t)ND * ND / 4;
    const size_t stride = (size_t)gridDim.x * blockDim.x;
    for (size_t idx = i; idx < 2 * n4; idx += stride) {
        bool isA = idx < n4;
        size_t j = isA ? idx : idx - n4;
        float4 v = isA ? ((const float4*)x)[j] : ((const float4*)w)[j];
        __half2* dst = isA ? (__half2*)g_qA : (__half2*)g_qB;
        dst[2 * j]     = __floats2half2_rn(v.x, v.y);
        dst[2 * j + 1] = __floats2half2_rn(v.z, v.w);
    }
    if (i < ND) g_qbias[i] = __half2float(__float2half_rn(b[i]));
}

// ---------------- GEMM ----------------
// Smem tile layout (A and B identical): row-major, 128 B per row (64 halves),
// 16-byte chunk c stored at (c ^ (row & 7)) — conflict-free for cp.async + ldmatrix.
__device__ __forceinline__ void load_stage(uint32_t stage_base, const __half* Ag,
                                           const __half* Bg, int kbase, int tid) {
#pragma unroll
    for (int i = 0; i < 8; ++i) {
        int c = tid + i * NTHREADS;          // 0..2047
        bool isA = c < 1024;
        int cc = c & 1023;
        int row = cc >> 3;
        int ch = cc & 7;
        uint32_t dst = stage_base + (isA ? 0u : (uint32_t)A_BYTES)
                     + (uint32_t)(row * 128) + (uint32_t)((ch ^ (row & 7)) << 4);
        const __half* src = (isA ? Ag : Bg) + (size_t)row * ND + kbase + ch * 8;
        asm volatile("cp.async.cg.shared.global [%0], [%1], 16;" :: "r"(dst), "l"(src));
    }
    asm volatile("cp.async.commit_group;" ::: "memory");
}

__global__ void __launch_bounds__(NTHREADS, 2)
qgemm_kernel(float* __restrict__ out) {
    extern __shared__ char smem_raw[];
    const uint32_t smem_base = smem_u32(smem_raw);

    const int tid = threadIdx.x;
    const int wid = tid >> 5;
    const int lane = tid & 31;
    const int tile_n = blockIdx.x;   // 0..31
    const int tile_m = blockIdx.y;   // 0..31

    const int wm = wid & 1;          // 2 warps along M -> 64 rows each
    const int wn = wid >> 1;         // 4 warps along N -> 32 cols each

    const __half* Ag = g_qA + (size_t)tile_m * BM * ND;
    const __half* Bg = g_qB + (size_t)tile_n * BN * ND;

    // Per-lane ldmatrix address components. XOR term depends only on lane.
    const uint32_t xorv = (uint32_t)(lane & 7);
    uint32_t a_row_off[4];
#pragma unroll
    for (int f = 0; f < 4; ++f)
        a_row_off[f] = (uint32_t)((wm * 64 + f * 16 + (lane & 15)) * 128);
    const uint32_t a_ch_base = (uint32_t)(lane >> 4);
    uint32_t b_row_off[2];
#pragma unroll
    for (int h = 0; h < 2; ++h)
        b_row_off[h] = (uint32_t)((wn * 32 + h * 16 + (lane & 7) + ((lane >> 4) & 1) * 8) * 128);
    const uint32_t b_ch_base = (uint32_t)((lane >> 3) & 1);

    float acc[4][4][4];
#pragma unroll
    for (int f = 0; f < 4; ++f)
#pragma unroll
        for (int g = 0; g < 4; ++g)
#pragma unroll
            for (int r = 0; r < 4; ++r) acc[f][g][r] = 0.0f;

    uint32_t a[4][4];        // A fragments, rotated in place (f-major reload)
    uint32_t bb[2][2][4];    // B fragments, double-buffered per k-step

    constexpr int NIT = ND / BK;   // 64

    // Prologue: 2 stages in flight
    load_stage(smem_base + 0 * STAGE_BYTES, Ag, Bg, 0 * BK, tid);
    load_stage(smem_base + 1 * STAGE_BYTES, Ag, Bg, 1 * BK, tid);

    int buf = 0;
    for (int it = 0; it < NIT; ++it) {
        if (it <= NIT - 2) asm volatile("cp.async.wait_group 1;" ::: "memory");
        else               asm volatile("cp.async.wait_group 0;" ::: "memory");
        __syncthreads();

        const uint32_t sA = smem_base + (uint32_t)(buf * STAGE_BYTES);
        const uint32_t sB = sA + A_BYTES;

        // ks=0 fragments first so MMAs can start ASAP.
#pragma unroll
        for (int f = 0; f < 4; ++f)
            ldmatrix_x4(a[f][0], a[f][1], a[f][2], a[f][3],
                        sA + a_row_off[f] + ((a_ch_base ^ xorv) << 4));
#pragma unroll
        for (int h = 0; h < 2; ++h)
            ldmatrix_x4(bb[0][h][0], bb[0][h][1], bb[0][h][2], bb[0][h][3],
                        sB + b_row_off[h] + ((b_ch_base ^ xorv) << 4));

        // Next-stage cp.async issues overlap with the MMAs below.
        const int nl = it + 2;
        if (nl < NIT) {
            int nb = buf + 2; if (nb >= STAGES) nb -= STAGES;
            load_stage(smem_base + (uint32_t)(nb * STAGE_BYTES), Ag, Bg, nl * BK, tid);
        }

#pragma unroll
        for (int ks = 0; ks < BK / 16; ++ks) {
            const int cb = ks & 1;
            // Prefetch B for ks+1 into the alternate buffer (16 MMA issues of cover).
            if (ks < BK / 16 - 1) {
                const uint32_t ks2 = (uint32_t)((ks + 1) * 2);
#pragma unroll
                for (int h = 0; h < 2; ++h)
                    ldmatrix_x4(bb[cb ^ 1][h][0], bb[cb ^ 1][h][1], bb[cb ^ 1][h][2],
                                bb[cb ^ 1][h][3],
                                sB + b_row_off[h] + (((ks2 + b_ch_base) ^ xorv) << 4));
            }
            // f-major MMAs; reload a[f] for ks+1 right after its last use this step.
#pragma unroll
            for (int f = 0; f < 4; ++f) {
#pragma unroll
                for (int g = 0; g < 4; ++g)
                    mma_16816(acc[f][g], a[f], bb[cb][g >> 1][(g & 1) * 2],
                              bb[cb][g >> 1][(g & 1) * 2 + 1]);
                if (ks < BK / 16 - 1) {
                    const uint32_t ks2 = (uint32_t)((ks + 1) * 2);
                    ldmatrix_x4(a[f][0], a[f][1], a[f][2], a[f][3],
                                sA + a_row_off[f] + (((ks2 + a_ch_base) ^ xorv) << 4));
                }
            }
        }

        if (++buf == STAGES) buf = 0;
    }

    // ---------------- epilogue ----------------
    const int row_base = tile_m * BM + wm * 64 + (lane >> 2);
    const int col_base = tile_n * BN + wn * 32 + 2 * (lane & 3);
#pragma unroll
    for (int f = 0; f < 4; ++f) {
#pragma unroll
        for (int g = 0; g < 4; ++g) {
            const int col = col_base + g * 8;
            const float2 bv = *(const float2*)(g_qbias + col);
            const int r0 = row_base + f * 16;
            float2 v0, v1;
            v0.x = acc[f][g][0] + bv.x;  v0.y = acc[f][g][1] + bv.y;
            v1.x = acc[f][g][2] + bv.x;  v1.y = acc[f][g][3] + bv.y;
            *(float2*)(out + (size_t)r0 * ND + col) = v0;
            *(float2*)(out + (size_t)(r0 + 8) * ND + col) = v1;
        }
    }
}

// ---------------- launch ----------------
extern "C" void kernel_launch(void* const* d_in, const int* in_sizes, int n_in,
                              void* d_out, int out_size) {
    const float* x = (const float*)d_in[0];
    const float* w = (const float*)d_in[1];
    const float* b = (const float*)d_in[2];
    float* out = (float*)d_out;

    quantize_kernel<<<4096, 256>>>(x, w, b);

    cudaFuncSetAttribute(qgemm_kernel, cudaFuncAttributeMaxDynamicSharedMemorySize, SMEM_BYTES);
    dim3 grid(ND / BN, ND / BM);   // 32 x 32 = 1024 CTAs
    qgemm_kernel<<<grid, NTHREADS, SMEM_BYTES>>>(out);
}

// round 10
// speedup vs baseline: 1.0419x; 1.0419x over previous
#include <cuda_runtime.h>
#include <cuda_fp16.h>
#include <cstdint>
#include <cstddef>

// out[4096,4096] = half(x)[4096,4096] @ half(W)^T + half(bias)
// E5M10 RNE quantize == __float2half_rn exactly for these inputs.
// Base sm_103 ISA (no tcgen05): cp.async + ldmatrix + mma.sync HMMA.
// R10: 128 threads / 4 warps, warp tile 64x64 (was 64x32) -> 1.5x less smem
//      crossbar traffic per FLOP; 3-stage ring, 2 CTAs/SM kept.

#define ND 4096

static constexpr int BM = 128;
static constexpr int BN = 128;
static constexpr int BK = 64;            // 64 halves = 128 B rows
static constexpr int STAGES = 3;
static constexpr int NTHREADS = 128;     // 4 warps

static constexpr int A_BYTES = BM * 128;              // 16 KB
static constexpr int B_BYTES = BN * 128;              // 16 KB
static constexpr int STAGE_BYTES = A_BYTES + B_BYTES; // 32 KB
static constexpr int SMEM_BYTES = STAGES * STAGE_BYTES; // 96 KB -> 2 CTAs/SM

// __device__ scratch (no runtime allocation allowed)
__device__ __half g_qA[(size_t)ND * ND];
__device__ __half g_qB[(size_t)ND * ND];
__device__ float  g_qbias[ND];

// ---------------- helpers ----------------
__device__ __forceinline__ uint32_t smem_u32(const void* p) {
    uint32_t a;
    asm("{ .reg .u64 t; cvta.to.shared.u64 t, %1; cvt.u32.u64 %0, t; }" : "=r"(a) : "l"(p));
    return a;
}

__device__ __forceinline__ void ldmatrix_x4(uint32_t& r0, uint32_t& r1, uint32_t& r2,
                                            uint32_t& r3, uint32_t addr) {
    asm volatile("ldmatrix.sync.aligned.m8n8.x4.shared.b16 {%0,%1,%2,%3}, [%4];"
                 : "=r"(r0), "=r"(r1), "=r"(r2), "=r"(r3) : "r"(addr));
}

__device__ __forceinline__ void mma_16816(float* c, const uint32_t* a,
                                          uint32_t b0, uint32_t b1) {
    asm volatile(
        "mma.sync.aligned.m16n8k16.row.col.f32.f16.f16.f32 "
        "{%0,%1,%2,%3}, {%4,%5,%6,%7}, {%8,%9}, {%0,%1,%2,%3};"
        : "+f"(c[0]), "+f"(c[1]), "+f"(c[2]), "+f"(c[3])
        : "r"(a[0]), "r"(a[1]), "r"(a[2]), "r"(a[3]), "r"(b0), "r"(b1));
}

// ---------------- quantize pass ----------------
__global__ void __launch_bounds__(256) quantize_kernel(
    const float* __restrict__ x, const float* __restrict__ w, const float* __restrict__ b) {
    size_t i = (size_t)blockIdx.x * blockDim.x + threadIdx.x;
    const size_t n4 = (size_t)ND * ND / 4;
    const size_t stride = (size_t)gridDim.x * blockDim.x;
    for (size_t idx = i; idx < 2 * n4; idx += stride) {
        bool isA = idx < n4;
        size_t j = isA ? idx : idx - n4;
        float4 v = isA ? ((const float4*)x)[j] : ((const float4*)w)[j];
        __half2* dst = isA ? (__half2*)g_qA : (__half2*)g_qB;
        dst[2 * j]     = __floats2half2_rn(v.x, v.y);
        dst[2 * j + 1] = __floats2half2_rn(v.z, v.w);
    }
    if (i < ND) g_qbias[i] = __half2float(__float2half_rn(b[i]));
}

// ---------------- GEMM ----------------
// Smem tile layout (A and B identical): row-major, 128 B per row (64 halves),
// 16-byte chunk c stored at (c ^ (row & 7)) — conflict-free for cp.async + ldmatrix.
__device__ __forceinline__ void load_stage(uint32_t stage_base, const __half* Ag,
                                           const __half* Bg, int kbase, int tid) {
#pragma unroll
    for (int i = 0; i < 16; ++i) {
        int c = tid + i * NTHREADS;          // 0..2047
        bool isA = c < 1024;
        int cc = c & 1023;
        int row = cc >> 3;
        int ch = cc & 7;
        uint32_t dst = stage_base + (isA ? 0u : (uint32_t)A_BYTES)
                     + (uint32_t)(row * 128) + (uint32_t)((ch ^ (row & 7)) << 4);
        const __half* src = (isA ? Ag : Bg) + (size_t)row * ND + kbase + ch * 8;
        asm volatile("cp.async.cg.shared.global [%0], [%1], 16;" :: "r"(dst), "l"(src));
    }
    asm volatile("cp.async.commit_group;" ::: "memory");
}

__global__ void __launch_bounds__(NTHREADS, 2)
qgemm_kernel(float* __restrict__ out) {
    extern __shared__ char smem_raw[];
    const uint32_t smem_base = smem_u32(smem_raw);

    const int tid = threadIdx.x;
    const int wid = tid >> 5;        // 0..3
    const int lane = tid & 31;
    const int tile_n = blockIdx.x;   // 0..31
    const int tile_m = blockIdx.y;   // 0..31

    const int wm = wid & 1;          // 2 warps along M -> 64 rows each
    const int wn = wid >> 1;         // 2 warps along N -> 64 cols each

    const __half* Ag = g_qA + (size_t)tile_m * BM * ND;
    const __half* Bg = g_qB + (size_t)tile_n * BN * ND;

    // Per-lane ldmatrix address components. XOR term depends only on lane.
    const uint32_t xorv = (uint32_t)(lane & 7);
    uint32_t a_row_off[4];
#pragma unroll
    for (int f = 0; f < 4; ++f)
        a_row_off[f] = (uint32_t)((wm * 64 + f * 16 + (lane & 15)) * 128);
    const uint32_t a_ch_base = (uint32_t)(lane >> 4);
    uint32_t b_row_off[4];
#pragma unroll
    for (int h = 0; h < 4; ++h)
        b_row_off[h] = (uint32_t)((wn * 64 + h * 16 + (lane & 7) + ((lane >> 4) & 1) * 8) * 128);
    const uint32_t b_ch_base = (uint32_t)((lane >> 3) & 1);

    float acc[4][8][4];
#pragma unroll
    for (int f = 0; f < 4; ++f)
#pragma unroll
        for (int g = 0; g < 8; ++g)
#pragma unroll
            for (int r = 0; r < 4; ++r) acc[f][g][r] = 0.0f;

    constexpr int NIT = ND / BK;   // 64

    // Prologue: 2 stages in flight
    load_stage(smem_base + 0 * STAGE_BYTES, Ag, Bg, 0 * BK, tid);
    load_stage(smem_base + 1 * STAGE_BYTES, Ag, Bg, 1 * BK, tid);

    int buf = 0;
    for (int it = 0; it < NIT; ++it) {
        if (it <= NIT - 2) asm volatile("cp.async.wait_group 1;" ::: "memory");
        else               asm volatile("cp.async.wait_group 0;" ::: "memory");
        __syncthreads();

        // Issue next-stage cp.async into the buffer consumed at it-1.
        const int nl = it + 2;
        if (nl < NIT) {
            int nb = buf + 2; if (nb >= STAGES) nb -= STAGES;
            load_stage(smem_base + (uint32_t)(nb * STAGE_BYTES), Ag, Bg, nl * BK, tid);
        }

        const uint32_t sA = smem_base + (uint32_t)(buf * STAGE_BYTES);
        const uint32_t sB = sA + A_BYTES;

#pragma unroll
        for (int ks = 0; ks < BK / 16; ++ks) {
            uint32_t a[4][4];
#pragma unroll
            for (int f = 0; f < 4; ++f) {
                uint32_t ch = (uint32_t)(ks * 2) + a_ch_base;
                ldmatrix_x4(a[f][0], a[f][1], a[f][2], a[f][3],
                            sA + a_row_off[f] + ((ch ^ xorv) << 4));
            }
            uint32_t bfrag[4][4];
#pragma unroll
            for (int h = 0; h < 4; ++h) {
                uint32_t ch = (uint32_t)(ks * 2) + b_ch_base;
                ldmatrix_x4(bfrag[h][0], bfrag[h][1], bfrag[h][2], bfrag[h][3],
                            sB + b_row_off[h] + ((ch ^ xorv) << 4));
            }
#pragma unroll
            for (int f = 0; f < 4; ++f)
#pragma unroll
                for (int g = 0; g < 8; ++g)
                    mma_16816(acc[f][g], a[f], bfrag[g >> 1][(g & 1) * 2],
                              bfrag[g >> 1][(g & 1) * 2 + 1]);
        }

        if (++buf == STAGES) buf = 0;
    }

    // ---------------- epilogue ----------------
    const int row_base = tile_m * BM + wm * 64 + (lane >> 2);
    const int col_base = tile_n * BN + wn * 64 + 2 * (lane & 3);
#pragma unroll
    for (int f = 0; f < 4; ++f) {
#pragma unroll
        for (int g = 0; g < 8; ++g) {
            const int col = col_base + g * 8;
            const float2 bv = *(const float2*)(g_qbias + col);
            const int r0 = row_base + f * 16;
            float2 v0, v1;
            v0.x = acc[f][g][0] + bv.x;  v0.y = acc[f][g][1] + bv.y;
            v1.x = acc[f][g][2] + bv.x;  v1.y = acc[f][g][3] + bv.y;
            *(float2*)(out + (size_t)r0 * ND + col) = v0;
            *(float2*)(out + (size_t)(r0 + 8) * ND + col) = v1;
        }
    }
}

// ---------------- launch ----------------
extern "C" void kernel_launch(void* const* d_in, const int* in_sizes, int n_in,
                              void* d_out, int out_size) {
    const float* x = (const float*)d_in[0];
    const float* w = (const float*)d_in[1];
    const float* b = (const float*)d_in[2];
    float* out = (float*)d_out;

    quantize_kernel<<<4096, 256>>>(x, w, b);

    cudaFuncSetAttribute(qgemm_kernel, cudaFuncAttributeMaxDynamicSharedMemorySize, SMEM_BYTES);
    dim3 grid(ND / BN, ND / BM);   // 32 x 32 = 1024 CTAs
    qgemm_kernel<<<grid, NTHREADS, SMEM_BYTES>>>(out);
}